// round 5
// baseline (speedup 1.0000x reference)
#include <cuda_runtime.h>
#include <cstdint>

// Problem constants (from reference: b=16, n=4096, d=64, h=1, c=2048)
#define N_TOK   65536
#define D       64
#define C_CODES 2048
#define BM      128          // token tile
#define BC      128          // code tile
#define THREADS 256
#define NCHUNK  (C_CODES / BC)   // 16

// Output layout (flattened concatenation, fp32):
// quantize [65536*64] | embed_ind [65536] | new_embeddings [2048*64]
// | new_cluster_size [2048] | new_embed_avg [2048*64]
#define OFF_Q    0
#define OFF_IND  (N_TOK * D)                    // 4194304
#define OFF_NE   (OFF_IND + N_TOK)              // 4259840
#define OFF_NCS  (OFF_NE + C_CODES * D)         // 4390912
#define OFF_NEA  (OFF_NCS + C_CODES)            // 4392960

#define SMEM_BYTES (( (64*128) + (64*128) + 128 ) * 4)   // xs + es + e2s = 66048 B

__device__ float g_e2[C_CODES];
__device__ float g_counts[C_CODES];

// ---------- packed f32x2 helpers ----------
__device__ __forceinline__ uint64_t pack_dup(float x) {
    uint64_t r;
    asm("mov.b64 %0, {%1, %1};" : "=l"(r) : "f"(x));
    return r;
}
__device__ __forceinline__ uint64_t pack2(float lo, float hi) {
    uint64_t r;
    asm("mov.b64 %0, {%1, %2};" : "=l"(r) : "f"(lo), "f"(hi));
    return r;
}
__device__ __forceinline__ void unpack2(uint64_t v, float& lo, float& hi) {
    asm("mov.b64 {%0, %1}, %2;" : "=f"(lo), "=f"(hi) : "l"(v));
}
__device__ __forceinline__ void ffma2(uint64_t& d, uint64_t a, uint64_t b) {
    asm("fma.rn.f32x2 %0, %1, %2, %0;" : "+l"(d) : "l"(a), "l"(b));
}

// ---------- kernel 1: init ----------
__global__ void vq_init(const float* __restrict__ E,
                        const float* __restrict__ ea,
                        float* __restrict__ outEA) {
    int gid = blockIdx.x * blockDim.x + threadIdx.x;
    int stride = gridDim.x * blockDim.x;
    // new_embed_avg initialized to DECAY * embed_avg; atomics add the 0.2*x later
    for (int i = gid; i < C_CODES * D; i += stride)
        outEA[i] = 0.8f * ea[i];
    for (int c = gid; c < C_CODES; c += stride) {
        const float4* p = reinterpret_cast<const float4*>(E + c * D);
        float s = 0.f;
        #pragma unroll
        for (int q = 0; q < D / 4; ++q) {
            float4 v = p[q];
            s += v.x * v.x + v.y * v.y + v.z * v.z + v.w * v.w;
        }
        g_e2[c] = s;
        g_counts[c] = 0.f;
    }
}

// ---------- kernel 2: fused distance GEMM + argmin + gather + scatter ----------
// smem: xs[64][128] k-major swizzled, es[64][128] k-major swizzled, e2s[128]
__global__ void __launch_bounds__(THREADS, 2)
vq_main(const float* __restrict__ x, const float* __restrict__ E,
        float* __restrict__ outQ, float* __restrict__ outInd,
        float* __restrict__ outEA) {
    extern __shared__ float smem[];
    float* xs  = smem;              // 8192 floats
    float* es  = smem + 64 * 128;   // 8192 floats
    float* e2s = smem + 2 * 64 * 128; // 128 floats

    const int tid  = threadIdx.x;
    const int row0 = (tid >> 4) * 8;   // token sub-tile base
    const int col0 = (tid & 15) * 8;   // code sub-tile base
    const int tokBase = blockIdx.x * BM;

    // ---- load x tile, transposed + swizzled: xs[k*128 + (r ^ ((k&15)*8))] ----
    {
        const float4* xsrc = reinterpret_cast<const float4*>(x + (size_t)tokBase * D);
        #pragma unroll
        for (int it = 0; it < (BM * (D / 4)) / THREADS; ++it) {
            int i  = tid + it * THREADS;
            int r  = i & 127;      // 32 consecutive rows per warp -> conflict-free STS
            int k4 = i >> 7;       // fixed within a warp
            float4 v = xsrc[r * (D / 4) + k4];
            int k = k4 * 4;
            xs[(k + 0) * 128 + (r ^ (((k + 0) & 15) * 8))] = v.x;
            xs[(k + 1) * 128 + (r ^ (((k + 1) & 15) * 8))] = v.y;
            xs[(k + 2) * 128 + (r ^ (((k + 2) & 15) * 8))] = v.z;
            xs[(k + 3) * 128 + (r ^ (((k + 3) & 15) * 8))] = v.w;
        }
    }

    float bestv[8];
    int   besti[8];
    #pragma unroll
    for (int i = 0; i < 8; ++i) { bestv[i] = 3.4e38f; besti[i] = 0; }

    for (int ch = 0; ch < NCHUNK; ++ch) {
        const int chBase = ch * BC;
        __syncthreads();   // xs stores done (first iter) / prev epilogue done

        // ---- load E chunk (128 codes x 64), same transposed+swizzled layout ----
        {
            const float4* esrc = reinterpret_cast<const float4*>(E + (size_t)chBase * D);
            #pragma unroll
            for (int it = 0; it < (BC * (D / 4)) / THREADS; ++it) {
                int i  = tid + it * THREADS;
                int r  = i & 127;
                int k4 = i >> 7;
                float4 v = esrc[r * (D / 4) + k4];
                int k = k4 * 4;
                es[(k + 0) * 128 + (r ^ (((k + 0) & 15) * 8))] = v.x;
                es[(k + 1) * 128 + (r ^ (((k + 1) & 15) * 8))] = v.y;
                es[(k + 2) * 128 + (r ^ (((k + 2) & 15) * 8))] = v.z;
                es[(k + 3) * 128 + (r ^ (((k + 3) & 15) * 8))] = v.w;
            }
            if (tid < BC) e2s[tid] = g_e2[chBase + tid];
        }
        __syncthreads();

        // ---- 128x128x64 GEMM fragment: acc[m][j] = row-pair (2m,2m+1) x col j ----
        uint64_t acc[4][8];
        #pragma unroll
        for (int m = 0; m < 4; ++m)
            #pragma unroll
            for (int j = 0; j < 8; ++j) acc[m][j] = 0ull;

        #pragma unroll 8
        for (int k = 0; k < D; ++k) {
            const int c = (k & 15) * 8;
            const float* xrow = xs + k * 128;
            const float* erow = es + k * 128;
            float4 a0 = *reinterpret_cast<const float4*>(xrow + (row0 ^ c));
            float4 a1 = *reinterpret_cast<const float4*>(xrow + ((row0 ^ c) + 4));
            float4 b0 = *reinterpret_cast<const float4*>(erow + (col0 ^ c));
            float4 b1 = *reinterpret_cast<const float4*>(erow + ((col0 ^ c) + 4));
            uint64_t a2[4];
            a2[0] = pack2(a0.x, a0.y); a2[1] = pack2(a0.z, a0.w);
            a2[2] = pack2(a1.x, a1.y); a2[3] = pack2(a1.z, a1.w);
            uint64_t bb[8];
            bb[0] = pack_dup(b0.x); bb[1] = pack_dup(b0.y);
            bb[2] = pack_dup(b0.z); bb[3] = pack_dup(b0.w);
            bb[4] = pack_dup(b1.x); bb[5] = pack_dup(b1.y);
            bb[6] = pack_dup(b1.z); bb[7] = pack_dup(b1.w);
            #pragma unroll
            for (int m = 0; m < 4; ++m)
                #pragma unroll
                for (int j = 0; j < 8; ++j)
                    ffma2(acc[m][j], a2[m], bb[j]);
        }

        // ---- running argmin update: val = e2[c] - 2*x.e  (x2 is a per-row const) ----
        #pragma unroll
        for (int m = 0; m < 4; ++m) {
            #pragma unroll
            for (int j = 0; j < 8; ++j) {
                float lo, hi;
                unpack2(acc[m][j], lo, hi);
                float e2v = e2s[col0 + j];
                float vlo = fmaf(-2.f, lo, e2v);
                float vhi = fmaf(-2.f, hi, e2v);
                int col = chBase + col0 + j;
                if (vlo < bestv[2 * m])     { bestv[2 * m]     = vlo; besti[2 * m]     = col; }
                if (vhi < bestv[2 * m + 1]) { bestv[2 * m + 1] = vhi; besti[2 * m + 1] = col; }
            }
        }
    }

    // ---- cross-thread argmin reduction (16 threads per token row) ----
    __syncthreads();
    float* rv = es;                       // 128*16 floats
    int*   ri = reinterpret_cast<int*>(es + 128 * 16);
    int*   s_idx = reinterpret_cast<int*>(xs);
    {
        const int tx = tid & 15;
        #pragma unroll
        for (int i = 0; i < 8; ++i) {
            int r = row0 + i;
            rv[r * 16 + tx] = bestv[i];
            ri[r * 16 + tx] = besti[i];
        }
    }
    __syncthreads();
    if (tid < BM) {
        float bv = rv[tid * 16];
        int   bi = ri[tid * 16];
        #pragma unroll
        for (int t = 1; t < 16; ++t) {
            float v = rv[tid * 16 + t];
            int   ix = ri[tid * 16 + t];
            if (v < bv || (v == bv && ix < bi)) { bv = v; bi = ix; }
        }
        s_idx[tid] = bi;
        outInd[tokBase + tid] = (float)bi;
        atomicAdd(&g_counts[bi], 1.0f);
    }
    __syncthreads();

    // ---- gather quantize + scatter (1-DECAY)*x into new_embed_avg ----
    for (int i = tid; i < BM * D; i += THREADS) {
        int r = i >> 6, k = i & 63;
        int ci = s_idx[r];
        int gtok = tokBase + r;
        float ev = E[(size_t)ci * D + k];
        outQ[(size_t)gtok * D + k] = ev;
        float xv = x[(size_t)gtok * D + k];
        atomicAdd(&outEA[(size_t)ci * D + k], 0.2f * xv);
    }
}

// ---------- kernel 3: EMA finalize + laplace smoothing + renormalize ----------
__global__ void vq_final(const float* __restrict__ cs,
                         const float* __restrict__ eaOut,
                         float* __restrict__ outNE,
                         float* __restrict__ outNCS) {
    __shared__ float s_ncs[C_CODES];
    __shared__ float s_red[32];
    const int tid = threadIdx.x;

    float local = 0.f;
    for (int c = tid; c < C_CODES; c += 1024) {
        float v = cs[c] * 0.8f + g_counts[c] * 0.2f;
        s_ncs[c] = v;
        outNCS[c] = v;
        local += v;
    }
    // block reduce -> tot
    #pragma unroll
    for (int o = 16; o > 0; o >>= 1)
        local += __shfl_down_sync(0xffffffffu, local, o);
    if ((tid & 31) == 0) s_red[tid >> 5] = local;
    __syncthreads();
    if (tid < 32) {
        float v = s_red[tid];
        #pragma unroll
        for (int o = 16; o > 0; o >>= 1)
            v += __shfl_down_sync(0xffffffffu, v, o);
        if (tid == 0) s_red[0] = v;
    }
    __syncthreads();
    float tot = s_red[0];
    __syncthreads();

    for (int c = tid; c < C_CODES; c += 1024) {
        float sm = (s_ncs[c] + 1e-5f) / (tot + (float)C_CODES * 1e-5f) * tot;
        s_ncs[c] = sm;
    }
    __syncthreads();
    for (int i = tid; i < C_CODES * D; i += 1024)
        outNE[i] = eaOut[i] / s_ncs[i >> 6];
}

// ---------- launch ----------
extern "C" void kernel_launch(void* const* d_in, const int* in_sizes, int n_in,
                              void* d_out, int out_size) {
    const float* x  = (const float*)d_in[0];
    const float* E  = (const float*)d_in[1];
    const float* cs = (const float*)d_in[2];
    const float* ea = (const float*)d_in[3];
    float* out = (float*)d_out;

    float* outQ   = out + OFF_Q;
    float* outInd = out + OFF_IND;
    float* outNE  = out + OFF_NE;
    float* outNCS = out + OFF_NCS;
    float* outEA  = out + OFF_NEA;

    cudaFuncSetAttribute(vq_main, cudaFuncAttributeMaxDynamicSharedMemorySize, SMEM_BYTES);

    vq_init<<<512, 256>>>(E, ea, outEA);
    vq_main<<<N_TOK / BM, THREADS, SMEM_BYTES>>>(x, E, outQ, outInd, outEA);
    vq_final<<<1, 1024>>>(cs, outEA, outNE, outNCS);
}

// round 9
// speedup vs baseline: 1.3312x; 1.3312x over previous
#include <cuda_runtime.h>
#include <cstdint>

// Problem constants (b=16, n=4096, d=64, h=1, c=2048)
#define N_TOK   65536
#define D       64
#define C_CODES 2048
#define BM      128
#define BC      128
#define NCHUNK  (C_CODES / BC)   // 16
#define THREADS 256

// Output layout (flattened, fp32):
#define OFF_Q    0
#define OFF_IND  (N_TOK * D)
#define OFF_NE   (OFF_IND + N_TOK)
#define OFF_NCS  (OFF_NE + C_CODES * D)
#define OFF_NEA  (OFF_NCS + C_CODES)

// ---- smem layout (float indices) ----
// A fragments: xh (8192) + xl (8192)   = 64 KB
// E stages:    2 x { eh 8192 | el 8192 } = 128 KB
// e2:          2 x 128
#define SF_AXH   0
#define SF_AXL   8192
#define SF_E(st) (16384 + (st) * 16384)   // eh at +0, el at +8192
#define SF_E2(st) (49152 + (st) * 128)
#define SMEM_FLOATS (49152 + 256)
#define SMEM_BYTES  (SMEM_FLOATS * 4)     // 197,632 B

// Fragment-layout scratch (written by vq_prep)
__device__ float g_xh[N_TOK * D];
__device__ float g_xl[N_TOK * D];
__device__ float g_eh[C_CODES * D];
__device__ float g_el[C_CODES * D];
__device__ float g_e2[C_CODES];
__device__ float g_counts[C_CODES];

// ---------- PTX helpers ----------
__device__ __forceinline__ uint32_t smem_u32(const void* p) {
    uint32_t a;
    asm("{ .reg .u64 t; cvta.to.shared.u64 t, %1; cvt.u32.u64 %0, t; }" : "=r"(a) : "l"(p));
    return a;
}
__device__ __forceinline__ float tf32_rna(float v) {
    uint32_t b;
    asm("cvt.rna.tf32.f32 %0, %1;" : "=r"(b) : "f"(v));
    return __uint_as_float(b);
}
__device__ __forceinline__ void mma8(float* d, const uint32_t* a, const uint32_t* b) {
    asm volatile(
        "mma.sync.aligned.m16n8k8.row.col.f32.tf32.tf32.f32 "
        "{%0,%1,%2,%3},{%4,%5,%6,%7},{%8,%9},{%0,%1,%2,%3};"
        : "+f"(d[0]), "+f"(d[1]), "+f"(d[2]), "+f"(d[3])
        : "r"(a[0]), "r"(a[1]), "r"(a[2]), "r"(a[3]), "r"(b[0]), "r"(b[1]));
}
__device__ __forceinline__ void lds4(uint32_t* r, uint32_t addr) {
    asm volatile("ld.shared.v4.b32 {%0,%1,%2,%3},[%4];"
                 : "=r"(r[0]), "=r"(r[1]), "=r"(r[2]), "=r"(r[3]) : "r"(addr));
}
__device__ __forceinline__ void lds2(uint32_t* r, uint32_t addr) {
    asm volatile("ld.shared.v2.b32 {%0,%1},[%2];"
                 : "=r"(r[0]), "=r"(r[1]) : "r"(addr));
}
__device__ __forceinline__ void cp16(uint32_t dst, const float* src) {
    asm volatile("cp.async.cg.shared.global [%0],[%1],16;"
                 :: "r"(dst), "l"(src) : "memory");
}
#define CP_COMMIT() asm volatile("cp.async.commit_group;" ::: "memory")
#define CP_WAIT0()  asm volatile("cp.async.wait_group 0;" ::: "memory")

// copies 2048 float4 (8192 floats) gmem -> smem, 256 threads
__device__ __forceinline__ void cp_bulk(uint32_t dst, const float* src, int tid) {
    #pragma unroll
    for (int t = 0; t < 8; ++t) {
        int i = tid + t * THREADS;
        cp16(dst + (uint32_t)i * 16, src + (size_t)i * 4);
    }
}

// ---------- kernel 1: split-precision prep into mma fragment layouts ----------
// A-frag (m16n8k8): within a 128x64 token tile, element (m,k) lives at
//   float_index = ((m_blk*8 + k_blk)*32 + lane)*4 + reg
//   lane = (m%8)*4 + (k%4), reg = ((m/8)%2) + 2*((k/4)%2)
// B-frag: within a 128x64 code chunk, element (n,k):
//   float_index = ((n_blk*8 + k_blk)*32 + lane)*2 + reg
//   lane = (n%8)*4 + (k%4), reg = (k%8)/4
__global__ void vq_prep(const float* __restrict__ x, const float* __restrict__ E,
                        const float* __restrict__ ea, float* __restrict__ outEA) {
    int gid = blockIdx.x * blockDim.x + threadIdx.x;
    int stride = gridDim.x * blockDim.x;

    // A-layout xh/xl: one float4 dest per work item
    const int NA = N_TOK * D / 4;
    for (int i = gid; i < NA; i += stride) {
        int tile = i >> 11, q = i & 2047;
        int lane = q & 31, kb = (q >> 5) & 7, mb = q >> 8;
        int gI = lane >> 2, t = lane & 3;
        int m0 = tile * 128 + mb * 16 + gI;
        int k0 = kb * 8 + t;
        const float* xp = x + (size_t)m0 * D + k0;
        float v0 = xp[0], v1 = xp[8 * D], v2 = xp[4], v3 = xp[8 * D + 4];
        float h0 = tf32_rna(v0), h1 = tf32_rna(v1), h2 = tf32_rna(v2), h3 = tf32_rna(v3);
        float4 H = make_float4(h0, h1, h2, h3);
        float4 L = make_float4(tf32_rna(v0 - h0), tf32_rna(v1 - h1),
                               tf32_rna(v2 - h2), tf32_rna(v3 - h3));
        reinterpret_cast<float4*>(g_xh)[i] = H;
        reinterpret_cast<float4*>(g_xl)[i] = L;
    }

    // B-layout eh/el: one float2 dest per work item
    const int NB = C_CODES * D / 2;
    for (int i = gid; i < NB; i += stride) {
        int chunk = i >> 12, q = i & 4095;
        int lane = q & 31, kb = (q >> 5) & 7, nb = q >> 8;
        int n0 = chunk * 128 + nb * 8 + (lane >> 2);
        int k0 = kb * 8 + (lane & 3);
        const float* ep = E + (size_t)n0 * D + k0;
        float v0 = ep[0], v1 = ep[4];
        float h0 = tf32_rna(v0), h1 = tf32_rna(v1);
        reinterpret_cast<float2*>(g_eh)[i] = make_float2(h0, h1);
        reinterpret_cast<float2*>(g_el)[i] = make_float2(tf32_rna(v0 - h0), tf32_rna(v1 - h1));
    }

    for (int i = gid; i < C_CODES * D; i += stride)
        outEA[i] = 0.8f * ea[i];

    for (int c = gid; c < C_CODES; c += stride) {
        const float4* p = reinterpret_cast<const float4*>(E + c * D);
        float s = 0.f;
        #pragma unroll
        for (int q = 0; q < D / 4; ++q) {
            float4 v = p[q];
            s += v.x * v.x + v.y * v.y + v.z * v.z + v.w * v.w;
        }
        g_e2[c] = s;
        g_counts[c] = 0.f;
    }
}

// ---------- kernel 2: tf32 mma.sync distance GEMM + argmin + gather + scatter ----------
__global__ void __launch_bounds__(THREADS, 1)
vq_main(const float* __restrict__ x, const float* __restrict__ E,
        float* __restrict__ outQ, float* __restrict__ outInd,
        float* __restrict__ outEA) {
    extern __shared__ float smemf[];
    uint32_t sb = smem_u32(smemf);

    const int tid = threadIdx.x;
    const int lane = tid & 31, wid = tid >> 5;
    const int warp_m = wid & 3, warp_n = wid >> 2;
    const int gI = lane >> 2, tig = lane & 3;
    const int tile = blockIdx.x;
    const int tokBase = tile * BM;

    // ---- prologue: A tiles + E chunk0 + e2 chunk0 via cp.async ----
    cp_bulk(sb + SF_AXH * 4, g_xh + (size_t)tile * 8192, tid);
    cp_bulk(sb + SF_AXL * 4, g_xl + (size_t)tile * 8192, tid);
    cp_bulk(sb + SF_E(0) * 4, g_eh, tid);
    cp_bulk(sb + SF_E(0) * 4 + 32768, g_el, tid);
    if (tid < 32) cp16(sb + SF_E2(0) * 4 + tid * 16, g_e2 + tid * 4);
    CP_COMMIT();

    float bestv[4];
    int   besti[4];
    #pragma unroll
    for (int r = 0; r < 4; ++r) { bestv[r] = 3.4e38f; besti[r] = 0; }

    for (int ch = 0; ch < NCHUNK; ++ch) {
        const int st = ch & 1, nst = st ^ 1;
        CP_WAIT0();
        __syncthreads();                       // stage st fully resident for all warps

        if (ch + 1 < NCHUNK) {                 // overlap next-chunk loads with compute
            cp_bulk(sb + SF_E(nst) * 4, g_eh + (size_t)(ch + 1) * 8192, tid);
            cp_bulk(sb + SF_E(nst) * 4 + 32768, g_el + (size_t)(ch + 1) * 8192, tid);
            if (tid < 32) cp16(sb + SF_E2(nst) * 4 + tid * 16, g_e2 + (ch + 1) * 128 + tid * 4);
            CP_COMMIT();
        }

        // ---- 128x128 x K=192 (3 tf32 passes of K=64) ----
        float acc[2][8][4];
        #pragma unroll
        for (int f = 0; f < 2; ++f)
            #pragma unroll
            for (int j = 0; j < 8; ++j)
                #pragma unroll
                for (int q = 0; q < 4; ++q) acc[f][j][q] = 0.f;

        #pragma unroll
        for (int pass = 0; pass < 3; ++pass) {
            const uint32_t aB = sb + ((pass == 2) ? SF_AXL : SF_AXH) * 4;
            const uint32_t bB = sb + SF_E(st) * 4 + ((pass == 1) ? 32768u : 0u);
            #pragma unroll
            for (int kb = 0; kb < 8; ++kb) {
                uint32_t a[2][4];
                #pragma unroll
                for (int f = 0; f < 2; ++f)
                    lds4(a[f], aB + (uint32_t)((((warp_m * 2 + f) * 8 + kb) * 32 + lane) << 4));
                uint32_t b[8][2];
                #pragma unroll
                for (int j = 0; j < 8; ++j)
                    lds2(b[j], bB + (uint32_t)((((warp_n * 8 + j) * 8 + kb) * 32 + lane) << 3));
                #pragma unroll
                for (int f = 0; f < 2; ++f)
                    #pragma unroll
                    for (int j = 0; j < 8; ++j)
                        mma8(acc[f][j], a[f], b[j]);
            }
        }

        // ---- epilogue: dist = e2[col] - 2*xe, running argmin in registers ----
        float e2v[16];
        #pragma unroll
        for (int j = 0; j < 8; ++j) {
            e2v[j * 2 + 0] = smemf[SF_E2(st) + warp_n * 64 + j * 8 + 2 * tig + 0];
            e2v[j * 2 + 1] = smemf[SF_E2(st) + warp_n * 64 + j * 8 + 2 * tig + 1];
        }
        const int colBase = ch * BC + warp_n * 64;
        #pragma unroll
        for (int f = 0; f < 2; ++f) {
            #pragma unroll
            for (int half = 0; half < 2; ++half) {
                const int r = f * 2 + half;
                #pragma unroll
                for (int j = 0; j < 8; ++j) {
                    #pragma unroll
                    for (int q = 0; q < 2; ++q) {
                        float dv = fmaf(-2.f, acc[f][j][half * 2 + q], e2v[j * 2 + q]);
                        int col = colBase + j * 8 + 2 * tig + q;
                        if (dv < bestv[r]) { bestv[r] = dv; besti[r] = col; }
                    }
                }
            }
        }
    }

    __syncthreads();   // done with smem tiles; reuse A region for reductions

    // ---- cross-lane argmin (over tig = lane%4) ----
    #pragma unroll
    for (int r = 0; r < 4; ++r) {
        #pragma unroll
        for (int off = 1; off <= 2; off <<= 1) {
            float ov = __shfl_xor_sync(0xffffffffu, bestv[r], off);
            int   oi = __shfl_xor_sync(0xffffffffu, besti[r], off);
            if (ov < bestv[r] || (ov == bestv[r] && oi < besti[r])) {
                bestv[r] = ov; besti[r] = oi;
            }
        }
    }

    float* sv0 = smemf;
    int*   si0 = reinterpret_cast<int*>(smemf + 128);
    float* sv1 = smemf + 256;
    int*   si1 = reinterpret_cast<int*>(smemf + 384);
    int*   s_idx = reinterpret_cast<int*>(smemf + 512);

    if (tig == 0) {
        #pragma unroll
        for (int f = 0; f < 2; ++f)
            #pragma unroll
            for (int half = 0; half < 2; ++half) {
                int r = f * 2 + half;
                int row = warp_m * 32 + f * 16 + half * 8 + gI;
                if (warp_n == 0) { sv0[row] = bestv[r]; si0[row] = besti[r]; }
                else             { sv1[row] = bestv[r]; si1[row] = besti[r]; }
            }
    }
    __syncthreads();

    if (tid < BM) {
        float v0 = sv0[tid], v1 = sv1[tid];
        int   i0 = si0[tid], i1 = si1[tid];
        int bi = (v1 < v0 || (v1 == v0 && i1 < i0)) ? i1 : i0;
        s_idx[tid] = bi;
        outInd[tokBase + tid] = (float)bi;
        atomicAdd(&g_counts[bi], 1.0f);
    }
    __syncthreads();

    // ---- gather quantize + scatter 0.2*x into new_embed_avg ----
    for (int i = tid; i < BM * D; i += THREADS) {
        int r = i >> 6, k = i & 63;
        int ci = s_idx[r];
        int gtok = tokBase + r;
        outQ[(size_t)gtok * D + k] = E[(size_t)ci * D + k];
        float xv = x[(size_t)gtok * D + k];
        atomicAdd(&outEA[(size_t)ci * D + k], 0.2f * xv);
    }
}

// ---------- kernel 3: EMA finalize + laplace smoothing + renormalize ----------
__global__ void vq_final(const float* __restrict__ cs,
                         const float* __restrict__ eaOut,
                         float* __restrict__ outNE,
                         float* __restrict__ outNCS) {
    __shared__ float s_ncs[C_CODES];
    __shared__ float s_red[32];
    const int tid = threadIdx.x;

    float local = 0.f;
    for (int c = tid; c < C_CODES; c += 1024) {
        float v = cs[c] * 0.8f + g_counts[c] * 0.2f;
        s_ncs[c] = v;
        outNCS[c] = v;
        local += v;
    }
    #pragma unroll
    for (int o = 16; o > 0; o >>= 1)
        local += __shfl_down_sync(0xffffffffu, local, o);
    if ((tid & 31) == 0) s_red[tid >> 5] = local;
    __syncthreads();
    if (tid < 32) {
        float v = s_red[tid];
        #pragma unroll
        for (int o = 16; o > 0; o >>= 1)
            v += __shfl_down_sync(0xffffffffu, v, o);
        if (tid == 0) s_red[0] = v;
    }
    __syncthreads();
    float tot = s_red[0];
    __syncthreads();

    for (int c = tid; c < C_CODES; c += 1024) {
        float sm = (s_ncs[c] + 1e-5f) / (tot + (float)C_CODES * 1e-5f) * tot;
        s_ncs[c] = sm;
    }
    __syncthreads();
    for (int i = tid; i < C_CODES * D; i += 1024)
        outNE[i] = eaOut[i] / s_ncs[i >> 6];
}

// ---------- launch ----------
extern "C" void kernel_launch(void* const* d_in, const int* in_sizes, int n_in,
                              void* d_out, int out_size) {
    const float* x  = (const float*)d_in[0];
    const float* E  = (const float*)d_in[1];
    const float* cs = (const float*)d_in[2];
    const float* ea = (const float*)d_in[3];
    float* out = (float*)d_out;

    float* outQ   = out + OFF_Q;
    float* outInd = out + OFF_IND;
    float* outNE  = out + OFF_NE;
    float* outNCS = out + OFF_NCS;
    float* outEA  = out + OFF_NEA;

    cudaFuncSetAttribute(vq_main, cudaFuncAttributeMaxDynamicSharedMemorySize, SMEM_BYTES);

    vq_prep<<<1024, 256>>>(x, E, ea, outEA);
    vq_main<<<N_TOK / BM, THREADS, SMEM_BYTES>>>(x, E, outQ, outInd, outEA);
    vq_final<<<1, 1024>>>(cs, outEA, outNE, outNCS);
}

// round 14
// speedup vs baseline: 1.4132x; 1.0616x over previous
#include <cuda_runtime.h>
#include <cuda_fp16.h>
#include <cstdint>

// Problem constants (b=16, n=4096, d=64, h=1, c=2048)
#define N_TOK   65536
#define D       64
#define C_CODES 2048
#define BM      128
#define BC      128
#define NCHUNK  (C_CODES / BC)   // 16
#define THREADS 256

// Output layout (flattened, fp32):
#define OFF_Q    0
#define OFF_IND  (N_TOK * D)
#define OFF_NE   (OFF_IND + N_TOK)
#define OFF_NCS  (OFF_NE + C_CODES * D)
#define OFF_NEA  (OFF_NCS + C_CODES)

// ---- smem layout (uint32 units) ----
#define SU_AXH   0
#define SU_AXL   4096
#define SU_E(st) (8192 + (st) * 8192)     // eh at +0, el at +4096
#define SU_E2(st) (24576 + (st) * 128)
#define SMEM_U32 (24832 + 512)
#define SMEM_BYTES (SMEM_U32 * 4)         // ~101 KB

#define RES_SCALE   4096.0f
#define RES_INV     0.000244140625f       // 2^-12
#define H_MIN_NORM  6.103515625e-5f       // 2^-14

// Fragment-layout scratch (written by vq_prep), packed half2 per u32
__device__ uint32_t g_xh[N_TOK * D / 2];
__device__ uint32_t g_xl[N_TOK * D / 2];
__device__ uint32_t g_eh[C_CODES * D / 2];
__device__ uint32_t g_el[C_CODES * D / 2];
__device__ float g_e2[C_CODES];
__device__ float g_counts[C_CODES];

// ---------- PTX helpers ----------
__device__ __forceinline__ uint32_t smem_u32(const void* p) {
    uint32_t a;
    asm("{ .reg .u64 t; cvta.to.shared.u64 t, %1; cvt.u32.u64 %0, t; }" : "=r"(a) : "l"(p));
    return a;
}
__device__ __forceinline__ void mma16(float* d, const uint32_t* a, const uint32_t* b) {
    asm volatile(
        "mma.sync.aligned.m16n8k16.row.col.f32.f16.f16.f32 "
        "{%0,%1,%2,%3},{%4,%5,%6,%7},{%8,%9},{%0,%1,%2,%3};"
        : "+f"(d[0]), "+f"(d[1]), "+f"(d[2]), "+f"(d[3])
        : "r"(a[0]), "r"(a[1]), "r"(a[2]), "r"(a[3]), "r"(b[0]), "r"(b[1]));
}
__device__ __forceinline__ void lds4(uint32_t* r, uint32_t addr) {
    asm volatile("ld.shared.v4.b32 {%0,%1,%2,%3},[%4];"
                 : "=r"(r[0]), "=r"(r[1]), "=r"(r[2]), "=r"(r[3]) : "r"(addr));
}
__device__ __forceinline__ void lds2(uint32_t* r, uint32_t addr) {
    asm volatile("ld.shared.v2.b32 {%0,%1},[%2];"
                 : "=r"(r[0]), "=r"(r[1]) : "r"(addr));
}
__device__ __forceinline__ void cp16(uint32_t dst, const void* src) {
    asm volatile("cp.async.cg.shared.global [%0],[%1],16;"
                 :: "r"(dst), "l"(src) : "memory");
}
#define CP_COMMIT() asm volatile("cp.async.commit_group;" ::: "memory")
#define CP_WAIT0()  asm volatile("cp.async.wait_group 0;" ::: "memory")

__device__ __forceinline__ void cp_bulk(uint32_t dst, const uint32_t* src, int tid, int cnt4) {
    for (int i = tid; i < cnt4; i += THREADS)
        cp16(dst + (uint32_t)i * 16, src + (size_t)i * 4);
}

// split x -> (h normal-range fp16, residual*4096 fp16)
__device__ __forceinline__ void split16(float v, __half& h, __half& l) {
    h = __float2half_rn(v);
    float hf = __half2float(h);
    if (fabsf(hf) < H_MIN_NORM) { h = __ushort_as_half((unsigned short)0); hf = 0.f; }
    l = __float2half_rn((v - hf) * RES_SCALE);
}

// top-2 update / merge (lexicographic on (value, index))
__device__ __forceinline__ void upd2(float d, int c, float& v1, int& i1, float& v2, int& i2) {
    if (d < v1) { v2 = v1; i2 = i1; v1 = d; i1 = c; }
    else if (d < v2) { v2 = d; i2 = c; }
}
__device__ __forceinline__ void merge2(float& v1, int& i1, float& v2, int& i2,
                                       float w1, int j1, float w2, int j2) {
    if (v1 < w1 || (v1 == w1 && i1 < j1)) {
        if (w1 < v2 || (w1 == v2 && j1 < i2)) { v2 = w1; i2 = j1; }
    } else {
        float nv2 = v1; int ni2 = i1;
        if (w2 < nv2 || (w2 == nv2 && j2 < ni2)) { nv2 = w2; ni2 = j2; }
        v1 = w1; i1 = j1; v2 = nv2; i2 = ni2;
    }
}

// ---------- kernel 1: fp16 split prep into m16n8k16 fragment layouts ----------
__global__ void vq_prep(const float* __restrict__ x, const float* __restrict__ E,
                        const float* __restrict__ ea, float* __restrict__ outEA) {
    int gid = blockIdx.x * blockDim.x + threadIdx.x;
    int stride = gridDim.x * blockDim.x;

    const int NA = N_TOK * D / 2;
    for (int i = gid; i < NA; i += stride) {
        int tile = i >> 12, q = i & 4095;
        int r = q & 3, lane = (q >> 2) & 31, kb = (q >> 7) & 3, mb = q >> 9;
        int m = tile * 128 + mb * 16 + (r & 1) * 8 + (lane >> 2);
        int k = kb * 16 + ((r >> 1) & 1) * 8 + (lane & 3) * 2;
        float2 v = *reinterpret_cast<const float2*>(x + (size_t)m * D + k);
        __half h0, l0, h1, l1;
        split16(v.x, h0, l0);
        split16(v.y, h1, l1);
        __half2 H = __halves2half2(h0, h1), L = __halves2half2(l0, l1);
        g_xh[i] = *reinterpret_cast<uint32_t*>(&H);
        g_xl[i] = *reinterpret_cast<uint32_t*>(&L);
    }

    const int NB = C_CODES * D / 2;
    for (int i = gid; i < NB; i += stride) {
        int chunk = i >> 12, q = i & 4095;
        int r = q & 1, lane = (q >> 1) & 31, kb = (q >> 6) & 3, nb = q >> 8;
        int n = chunk * 128 + nb * 8 + (lane >> 2);
        int k = kb * 16 + r * 8 + (lane & 3) * 2;
        float2 v = *reinterpret_cast<const float2*>(E + (size_t)n * D + k);
        __half h0, l0, h1, l1;
        split16(v.x, h0, l0);
        split16(v.y, h1, l1);
        __half2 H = __halves2half2(h0, h1), L = __halves2half2(l0, l1);
        g_eh[i] = *reinterpret_cast<uint32_t*>(&H);
        g_el[i] = *reinterpret_cast<uint32_t*>(&L);
    }

    for (int i = gid; i < C_CODES * D; i += stride)
        outEA[i] = 0.8f * ea[i];

    for (int c = gid; c < C_CODES; c += stride) {
        const float4* p = reinterpret_cast<const float4*>(E + c * D);
        float s = 0.f;
        #pragma unroll
        for (int q = 0; q < D / 4; ++q) {
            float4 v = p[q];
            s += v.x * v.x + v.y * v.y + v.z * v.z + v.w * v.w;
        }
        g_e2[c] = s;
        g_counts[c] = 0.f;
    }
}

// ---------- kernel 2: fp16x3 mma.sync GEMM + top2 argmin + fp32 rescue ----------
__global__ void __launch_bounds__(THREADS, 2)
vq_main(const float* __restrict__ x, const float* __restrict__ E,
        float* __restrict__ outQ, float* __restrict__ outInd,
        float* __restrict__ outEA) {
    extern __shared__ uint32_t smemu[];
    uint32_t sb = smem_u32(smemu);
    float* smemf = reinterpret_cast<float*>(smemu);

    const int tid = threadIdx.x;
    const int lane = tid & 31, wid = tid >> 5;
    const int warp_m = wid & 3, warp_n = wid >> 2;
    const int gI = lane >> 2, tig = lane & 3;
    const int tile = blockIdx.x;
    const int tokBase = tile * BM;

    // ---- prologue: A tiles + E chunk0 + e2 chunk0 via cp.async ----
    cp_bulk(sb + SU_AXH * 4, g_xh + (size_t)tile * 4096, tid, 1024);
    cp_bulk(sb + SU_AXL * 4, g_xl + (size_t)tile * 4096, tid, 1024);
    cp_bulk(sb + SU_E(0) * 4, g_eh, tid, 1024);
    cp_bulk(sb + SU_E(0) * 4 + 16384, g_el, tid, 1024);
    if (tid < 32) cp16(sb + SU_E2(0) * 4 + tid * 16, g_e2 + tid * 4);
    CP_COMMIT();

    float bv1[4], bv2[4];
    int   bi1[4], bi2[4];
    #pragma unroll
    for (int r = 0; r < 4; ++r) { bv1[r] = bv2[r] = 3.4e38f; bi1[r] = bi2[r] = 0; }

    for (int ch = 0; ch < NCHUNK; ++ch) {
        const int st = ch & 1, nst = st ^ 1;
        CP_WAIT0();
        __syncthreads();

        if (ch + 1 < NCHUNK) {
            cp_bulk(sb + SU_E(nst) * 4, g_eh + (size_t)(ch + 1) * 4096, tid, 1024);
            cp_bulk(sb + SU_E(nst) * 4 + 16384, g_el + (size_t)(ch + 1) * 4096, tid, 1024);
            if (tid < 32) cp16(sb + SU_E2(nst) * 4 + tid * 16, g_e2 + (ch + 1) * 128 + tid * 4);
            CP_COMMIT();
        }

        // ---- pass0: xl_s*eh, pass1: xh*el_s, scale by 2^-12, pass2: xh*eh ----
        float acc[2][8][4];
        #pragma unroll
        for (int f = 0; f < 2; ++f)
            #pragma unroll
            for (int j = 0; j < 8; ++j)
                #pragma unroll
                for (int q = 0; q < 4; ++q) acc[f][j][q] = 0.f;

        #pragma unroll
        for (int pass = 0; pass < 3; ++pass) {
            const uint32_t aB = sb + ((pass == 0) ? SU_AXL : SU_AXH) * 4;
            const uint32_t bB = sb + SU_E(st) * 4 + ((pass == 1) ? 16384u : 0u);
            #pragma unroll
            for (int kb = 0; kb < 4; ++kb) {
                uint32_t a[2][4];
                #pragma unroll
                for (int f = 0; f < 2; ++f)
                    lds4(a[f], aB + (uint32_t)((((warp_m * 2 + f) * 4 + kb) * 32 + lane) << 4));
                uint32_t b[8][2];
                #pragma unroll
                for (int j = 0; j < 8; ++j)
                    lds2(b[j], bB + (uint32_t)((((warp_n * 8 + j) * 4 + kb) * 32 + lane) << 3));
                #pragma unroll
                for (int f = 0; f < 2; ++f)
                    #pragma unroll
                    for (int j = 0; j < 8; ++j)
                        mma16(acc[f][j], a[f], b[j]);
            }
            if (pass == 1) {
                #pragma unroll
                for (int f = 0; f < 2; ++f)
                    #pragma unroll
                    for (int j = 0; j < 8; ++j)
                        #pragma unroll
                        for (int q = 0; q < 4; ++q) acc[f][j][q] *= RES_INV;
            }
        }

        // ---- epilogue: dist = e2[col] - 2*xe, running top-2 ----
        const int colBase = ch * BC + warp_n * 64;
        #pragma unroll
        for (int j = 0; j < 8; ++j) {
            float e2a = smemf[SU_E2(st) + warp_n * 64 + j * 8 + 2 * tig + 0];
            float e2b = smemf[SU_E2(st) + warp_n * 64 + j * 8 + 2 * tig + 1];
            #pragma unroll
            for (int f = 0; f < 2; ++f) {
                #pragma unroll
                for (int half = 0; half < 2; ++half) {
                    const int r = f * 2 + half;
                    float d0 = fmaf(-2.f, acc[f][j][half * 2 + 0], e2a);
                    float d1 = fmaf(-2.f, acc[f][j][half * 2 + 1], e2b);
                    int c0 = colBase + j * 8 + 2 * tig;
                    upd2(d0, c0,     bv1[r], bi1[r], bv2[r], bi2[r]);
                    upd2(d1, c0 + 1, bv1[r], bi1[r], bv2[r], bi2[r]);
                }
            }
        }
    }

    __syncthreads();   // tiles no longer needed; reuse smem for reductions

    // ---- cross-lane top-2 merge (over tig) ----
    #pragma unroll
    for (int r = 0; r < 4; ++r) {
        #pragma unroll
        for (int off = 1; off <= 2; off <<= 1) {
            float w1 = __shfl_xor_sync(0xffffffffu, bv1[r], off);
            float w2 = __shfl_xor_sync(0xffffffffu, bv2[r], off);
            int   j1 = __shfl_xor_sync(0xffffffffu, bi1[r], off);
            int   j2 = __shfl_xor_sync(0xffffffffu, bi2[r], off);
            merge2(bv1[r], bi1[r], bv2[r], bi2[r], w1, j1, w2, j2);
        }
    }

    float* sv1 = smemf;                                 // [2][128]
    float* sv2 = smemf + 256;                           // [2][128]
    int*   si1 = reinterpret_cast<int*>(smemf + 512);   // [2][128]
    int*   si2 = reinterpret_cast<int*>(smemf + 768);   // [2][128]
    int*   sc1 = reinterpret_cast<int*>(smemf + 1024);  // [128] candidate 1
    int*   sc2 = reinterpret_cast<int*>(smemf + 1152);  // [128] candidate 2
    int*   s_fin = reinterpret_cast<int*>(smemf + 1280);// [128] final index

    if (tig == 0) {
        #pragma unroll
        for (int f = 0; f < 2; ++f)
            #pragma unroll
            for (int half = 0; half < 2; ++half) {
                int r = f * 2 + half;
                int row = warp_m * 32 + f * 16 + half * 8 + gI;
                sv1[warp_n * 128 + row] = bv1[r];
                sv2[warp_n * 128 + row] = bv2[r];
                si1[warp_n * 128 + row] = bi1[r];
                si2[warp_n * 128 + row] = bi2[r];
            }
    }
    __syncthreads();

    if (tid < BM) {
        float v1 = sv1[tid], v2 = sv2[tid];
        int   i1 = si1[tid], i2 = si2[tid];
        merge2(v1, i1, v2, i2, sv1[128 + tid], si1[128 + tid],
               sv2[128 + tid], si2[128 + tid]);
        sc1[tid] = i1;
        sc2[tid] = i2;
    }
    __syncthreads();

    // ---- exact fp32 rescue: 2 threads per token re-evaluate the top-2 ----
    {
        int r = tid >> 1;
        int cand = (tid & 1) ? sc2[r] : sc1[r];
        const float4* xr = reinterpret_cast<const float4*>(x + (size_t)(tokBase + r) * D);
        const float4* er = reinterpret_cast<const float4*>(E + (size_t)cand * D);
        float4 s = make_float4(0.f, 0.f, 0.f, 0.f);
        #pragma unroll
        for (int q = 0; q < D / 4; ++q) {
            float4 a = xr[q], b = er[q];
            s.x = fmaf(a.x, b.x, s.x);
            s.y = fmaf(a.y, b.y, s.y);
            s.z = fmaf(a.z, b.z, s.z);
            s.w = fmaf(a.w, b.w, s.w);
        }
        float dot = (s.x + s.y) + (s.z + s.w);
        float dv = fmaf(-2.f, dot, __ldg(&g_e2[cand]));
        float ov = __shfl_xor_sync(0xffffffffu, dv, 1);
        int   oc = __shfl_xor_sync(0xffffffffu, cand, 1);
        int bi = (dv < ov || (dv == ov && cand < oc)) ? cand : oc;
        if ((tid & 1) == 0) {
            s_fin[r] = bi;
            outInd[tokBase + r] = (float)bi;
            atomicAdd(&g_counts[bi], 1.0f);
        }
    }
    __syncthreads();

    // ---- gather quantize + scatter 0.2*x into new_embed_avg ----
    for (int i = tid; i < BM * D; i += THREADS) {
        int r = i >> 6, k = i & 63;
        int ci = s_fin[r];
        int gtok = tokBase + r;
        outQ[(size_t)gtok * D + k] = E[(size_t)ci * D + k];
        float xv = x[(size_t)gtok * D + k];
        atomicAdd(&outEA[(size_t)ci * D + k], 0.2f * xv);
    }
}

// ---------- kernel 3: EMA finalize + laplace smoothing + renormalize ----------
__global__ void vq_final(const float* __restrict__ cs,
                         const float* __restrict__ eaOut,
                         float* __restrict__ outNE,
                         float* __restrict__ outNCS) {
    __shared__ float s_ncs[C_CODES];
    __shared__ float s_red[32];
    const int tid = threadIdx.x;

    float local = 0.f;
    for (int c = tid; c < C_CODES; c += 1024) {
        float v = cs[c] * 0.8f + g_counts[c] * 0.2f;
        s_ncs[c] = v;
        outNCS[c] = v;
        local += v;
    }
    #pragma unroll
    for (int o = 16; o > 0; o >>= 1)
        local += __shfl_down_sync(0xffffffffu, local, o);
    if ((tid & 31) == 0) s_red[tid >> 5] = local;
    __syncthreads();
    if (tid < 32) {
        float v = s_red[tid];
        #pragma unroll
        for (int o = 16; o > 0; o >>= 1)
            v += __shfl_down_sync(0xffffffffu, v, o);
        if (tid == 0) s_red[0] = v;
    }
    __syncthreads();
    float tot = s_red[0];
    __syncthreads();

    for (int c = tid; c < C_CODES; c += 1024) {
        float sm = (s_ncs[c] + 1e-5f) / (tot + (float)C_CODES * 1e-5f) * tot;
        s_ncs[c] = sm;
    }
    __syncthreads();
    for (int i = tid; i < C_CODES * D; i += 1024)
        outNE[i] = eaOut[i] / s_ncs[i >> 6];
}

// ---------- launch ----------
extern "C" void kernel_launch(void* const* d_in, const int* in_sizes, int n_in,
                              void* d_out, int out_size) {
    const float* x  = (const float*)d_in[0];
    const float* E  = (const float*)d_in[1];
    const float* cs = (const float*)d_in[2];
    const float* ea = (const float*)d_in[3];
    float* out = (float*)d_out;

    float* outQ   = out + OFF_Q;
    float* outInd = out + OFF_IND;
    float* outNE  = out + OFF_NE;
    float* outNCS = out + OFF_NCS;
    float* outEA  = out + OFF_NEA;

    cudaFuncSetAttribute(vq_main, cudaFuncAttributeMaxDynamicSharedMemorySize, SMEM_BYTES);

    vq_prep<<<1024, 256>>>(x, E, ea, outEA);
    vq_main<<<N_TOK / BM, THREADS, SMEM_BYTES>>>(x, E, outQ, outInd, outEA);
    vq_final<<<1, 1024>>>(cs, outEA, outNE, outNCS);
}